// round 15
// baseline (speedup 1.0000x reference)
#include <cuda_runtime.h>
#include <cuda_bf16.h>
#include <cstdint>

// Problem constants
#define DN   128      // embedding dim
#define CN   50       // conv channels
#define RNUM 237      // relations
#define BNUM 16384    // triples
#define TB   32       // triple slots per CTA (MMA M = 64 = 32 h + 32 t)
#define NCHK 4        // chunks per relation (capacity 128)
#define NTHR 256      // 8 warps

// ---- device scratch ----
__device__ int g_count[RNUM];   // zero at module load; k_scan resets it each run
__device__ int g_start[RNUM];
__device__ int g_cnt[RNUM];
__device__ int g_cursor[RNUM];
__device__ int g_sorted[BNUM];

// ---------------------------------------------------------------------------
// Prep: hist -> scan(+reset) -> aggregated scatter  (proven)
// ---------------------------------------------------------------------------
__global__ void k_hist(const int* __restrict__ triples) {
    __shared__ int sh[RNUM];
    for (int i = threadIdx.x; i < RNUM; i += blockDim.x) sh[i] = 0;
    __syncthreads();
    int i = blockIdx.x * blockDim.x + threadIdx.x;
    if (i < BNUM) atomicAdd(&sh[triples[3 * i + 1]], 1);
    __syncthreads();
    for (int i2 = threadIdx.x; i2 < RNUM; i2 += blockDim.x) {
        int v = sh[i2];
        if (v) atomicAdd(&g_count[i2], v);
    }
}

__global__ void k_scan() {
    int l = threadIdx.x;
    int vals[8], cnts[8];
    int sum = 0;
#pragma unroll
    for (int j = 0; j < 8; j++) {
        int b = l * 8 + j;
        vals[j] = sum;
        cnts[j] = (b < RNUM) ? g_count[b] : 0;
        sum += cnts[j];
    }
    int x = sum;
#pragma unroll
    for (int sft = 1; sft < 32; sft <<= 1) {
        int y = __shfl_up_sync(0xffffffffu, x, sft);
        if (l >= sft) x += y;
    }
    int off = x - sum;
#pragma unroll
    for (int j = 0; j < 8; j++) {
        int b = l * 8 + j;
        if (b < RNUM) {
            int s = off + vals[j];
            g_start[b]  = s;
            g_cursor[b] = s;
            g_cnt[b]    = cnts[j];
            g_count[b]  = 0;
        }
    }
}

__global__ void k_scatter(const int* __restrict__ triples) {
    __shared__ int lcnt[RNUM];
    __shared__ int lcur[RNUM];
    const int tid = threadIdx.x;
    for (int i = tid; i < RNUM; i += 512) lcnt[i] = 0;
    __syncthreads();
    const int i = blockIdx.x * 512 + tid;
    const int r = triples[3 * i + 1];
    atomicAdd(&lcnt[r], 1);
    __syncthreads();
    for (int b = tid; b < RNUM; b += 512) {
        int c = lcnt[b];
        int base = c ? atomicAdd(&g_cursor[b], c) : 0;
        lcur[b] = base;
    }
    __syncthreads();
    int pos = atomicAdd(&lcur[r], 1);
    g_sorted[pos] = i;
}

// ---------------------------------------------------------------------------
// MMA helpers (generic PTX: ldmatrix + mma.sync bf16 — compiles at compute_103)
// ---------------------------------------------------------------------------
__device__ __forceinline__ uint32_t smem_u32(const void* p) {
    uint32_t a;
    asm("{ .reg .u64 t; cvta.to.shared.u64 t, %1; cvt.u32.u64 %0, t; }" : "=r"(a) : "l"(p));
    return a;
}
__device__ __forceinline__ void ldsm4(unsigned* f, uint32_t addr) {
    asm volatile("ldmatrix.sync.aligned.m8n8.x4.shared.b16 {%0,%1,%2,%3}, [%4];"
                 : "=r"(f[0]), "=r"(f[1]), "=r"(f[2]), "=r"(f[3]) : "r"(addr));
}
__device__ __forceinline__ void ldsm4t(unsigned* f, uint32_t addr) {
    asm volatile("ldmatrix.sync.aligned.m8n8.x4.trans.shared.b16 {%0,%1,%2,%3}, [%4];"
                 : "=r"(f[0]), "=r"(f[1]), "=r"(f[2]), "=r"(f[3]) : "r"(addr));
}
__device__ __forceinline__ void mma16816(float* c, const unsigned* a, unsigned b0, unsigned b1) {
    asm volatile(
        "mma.sync.aligned.m16n8k16.row.col.f32.bf16.bf16.f32 "
        "{%0,%1,%2,%3}, {%4,%5,%6,%7}, {%8,%9}, {%0,%1,%2,%3};"
        : "+f"(c[0]), "+f"(c[1]), "+f"(c[2]), "+f"(c[3])
        : "r"(a[0]), "r"(a[1]), "r"(a[2]), "r"(a[3]), "r"(b0), "r"(b1));
}

// f32 pair -> bf16x2 hi + bf16x2 lo (split precision)
__device__ __forceinline__ void cvt2(float a, float b, unsigned& hi, unsigned& lo) {
    __nv_bfloat16 ah = __float2bfloat16_rn(a);
    __nv_bfloat16 bh = __float2bfloat16_rn(b);
    float ar = a - __bfloat162float(ah);
    float br = b - __bfloat162float(bh);
    __nv_bfloat162 H; H.x = ah; H.y = bh;
    __nv_bfloat162 L; L.x = __float2bfloat16_rn(ar); L.y = __float2bfloat16_rn(br);
    hi = *reinterpret_cast<unsigned*>(&H);
    lo = *reinterpret_cast<unsigned*>(&L);
}

// smem layout (bytes). bf16 tiles, row stride 272B
#define TSTR    272
#define ATILE_B (64 * TSTR)        // 17408  (A: 64 rows)
#define BTILE_B (128 * TSTR)       // 34816  (B: 128 rows)
#define OFF_AH  0
#define OFF_AL  (ATILE_B)          // 17408
#define OFF_BH  (2 * ATILE_B)      // 34816
#define OFF_BL  (2 * ATILE_B + BTILE_B)   // 69632
#define OFF_D   0                  // fp32 64 x 132 (33792 B) — overlays A after MMA
#define SD_STRIDE 132
#define OFF_REL (OFF_BL + BTILE_B) // 104448
#define OFF_CP  (OFF_REL + 512)    // 104960
#define OFF_TID (OFF_CP + 800)     // 105760
#define SMEM_BYTES (OFF_TID + 128) // 105888

__global__ __launch_bounds__(NTHR, 2)
void k_main(const int* __restrict__ triples,
            const float* __restrict__ ent_emb,
            const float* __restrict__ rel_emb,
            const float* __restrict__ rel_W,
            const float* __restrict__ conv_w,
            const float* __restrict__ conv_b,
            const float* __restrict__ fc_w,
            const float* __restrict__ fc_b,
            float* __restrict__ out)
{
    const int r     = blockIdx.x >> 2;
    const int chunk = blockIdx.x & 3;

    const int cnt  = g_cnt[r];
    const int base = chunk * TB;
    const int n    = min(TB, cnt - base);
    if (n <= 0) return;                 // ~45% of CTAs exit immediately
    const int gbase = g_start[r] + base;

    extern __shared__ char smc[];
    float* sD   = (float*)(smc + OFF_D);
    float* sRel = (float*)(smc + OFF_REL);
    float* sCp  = (float*)(smc + OFF_CP);
    int*   sTid = (int*)(smc + OFF_TID);

    const int tid  = threadIdx.x;
    const int wid  = tid >> 5;          // 0..7
    const int lane = tid & 31;
    const uint32_t sbase = smem_u32(smc);

    // ---- stage Wr natural [d][e] as bf16 hi/lo ----
    {
        const int e2 = (tid & 63) * 2;          // e pair
        const int dg = tid >> 6;                // 0..3 -> 32 d-rows each
        const float* Wb = rel_W + (size_t)r * DN * DN;
#pragma unroll 4
        for (int dd = 0; dd < 32; dd++) {
            int d = dg * 32 + dd;
            float2 v = *(const float2*)(Wb + (size_t)d * DN + e2);
            unsigned H, L;
            cvt2(v.x, v.y, H, L);
            *(unsigned*)(smc + OFF_BH + d * TSTR + e2 * 2) = H;
            *(unsigned*)(smc + OFF_BL + d * TSTR + e2 * 2) = L;
        }
    }

    // ---- stage entities [slot][d] bf16 hi/lo: rows 0..31 = h, 32..63 = t ----
    {
        const int rp = tid >> 2;                 // row 0..63
        const int q4 = tid & 3;                  // col quarter (32 cols)
        const int c0 = q4 * 32;
        const int slot = rp & 31;
        const bool isH = rp < 32;
        if (slot < n) {
            int i = g_sorted[gbase + slot];
            if (isH && q4 == 0) sTid[slot] = i;
            int ent = isH ? triples[3 * i] : triples[3 * i + 2];
            const float4* ev = (const float4*)(ent_emb + (size_t)ent * DN);
#pragma unroll
            for (int b = 0; b < 4; b++) {
                float4 u = ev[(c0 >> 2) + 2 * b];
                float4 v = ev[(c0 >> 2) + 2 * b + 1];
                unsigned h0,l0,h1,l1,h2,l2,h3,l3;
                cvt2(u.x, u.y, h0, l0); cvt2(u.z, u.w, h1, l1);
                cvt2(v.x, v.y, h2, l2); cvt2(v.z, v.w, h3, l3);
                uint4 H = make_uint4(h0, h1, h2, h3);
                uint4 L = make_uint4(l0, l1, l2, l3);
                int o = rp * TSTR + (c0 + 8 * b) * 2;
                *(uint4*)(smc + OFF_AH + o) = H;
                *(uint4*)(smc + OFF_AL + o) = L;
            }
        } else {
            uint4 Z = make_uint4(0, 0, 0, 0);
#pragma unroll
            for (int b = 0; b < 4; b++) {
                int o = rp * TSTR + (c0 + 8 * b) * 2;
                *(uint4*)(smc + OFF_AH + o) = Z;
                *(uint4*)(smc + OFF_AL + o) = Z;
            }
        }
    }

    // ---- stage rel_emb + packed conv params ----
    if (tid < 32) ((float4*)sRel)[tid] = ((const float4*)(rel_emb + (size_t)r * DN))[tid];
    if (tid < CN) {
        float4 cp;
        cp.x = conv_w[3 * tid + 0];
        cp.y = conv_w[3 * tid + 1];
        cp.z = conv_w[3 * tid + 2];
        cp.w = conv_b[tid];
        ((float4*)sCp)[tid] = cp;
    }
    __syncthreads();

    // ---- MMA: warp w -> m-tile (w&3)*16, n-half (w>>2)*64 ----
    // D = Ah*Bh + Al*Bh + Ah*Bl   (validated R11 addressing)
    const int m0 = (wid & 3) * 16;
    const int nb = (wid >> 2) * 64;

    float acc[8][4];
#pragma unroll
    for (int tI = 0; tI < 8; tI++)
#pragma unroll
        for (int j = 0; j < 4; j++) acc[tI][j] = 0.f;

    const uint32_t aRow = m0 + ((lane >> 3) & 1) * 8 + (lane & 7);
    const uint32_t aCol16 = (lane >> 4) << 4;
    const uint32_t bDrow = ((lane >> 3) & 1) * 8 + (lane & 7);
    const uint32_t bEoff = ((lane >> 4) << 3) * 2;

#pragma unroll
    for (int k0 = 0; k0 < 8; k0++) {
        unsigned ah[4], al[4];
        {
            uint32_t ad = sbase + aRow * TSTR + k0 * 32 + aCol16;
            ldsm4(ah, ad + OFF_AH);
            ldsm4(al, ad + OFF_AL);
        }
#pragma unroll
        for (int np = 0; np < 4; np++) {
            const int n0 = nb + np * 16;
            unsigned bh[4], bl[4];
            uint32_t bd = sbase + (k0 * 16 + bDrow) * TSTR + n0 * 2 + bEoff;
            ldsm4t(bh, bd + OFF_BH);
            ldsm4t(bl, bd + OFF_BL);
            float* c0 = acc[np * 2];
            float* c1 = acc[np * 2 + 1];
            mma16816(c0, ah, bh[0], bh[1]);
            mma16816(c1, ah, bh[2], bh[3]);
            mma16816(c0, al, bh[0], bh[1]);
            mma16816(c1, al, bh[2], bh[3]);
            mma16816(c0, ah, bl[0], bl[1]);
            mma16816(c1, ah, bl[2], bl[3]);
        }
    }
    __syncthreads();   // all warps done reading A before sD overlays it

    // ---- store accumulators to sD[row][col] (stride 132) ----
    {
        const int g  = lane >> 2;
        const int tg = lane & 3;
#pragma unroll
        for (int np = 0; np < 4; np++) {
#pragma unroll
            for (int t = 0; t < 2; t++) {
                const float* c = acc[np * 2 + t];
                int col = nb + np * 16 + t * 8 + 2 * tg;
                *(float2*)(sD + (m0 + g) * SD_STRIDE + col)     = make_float2(c[0], c[1]);
                *(float2*)(sD + (m0 + 8 + g) * SD_STRIDE + col) = make_float2(c[2], c[3]);
            }
        }
    }
    __syncthreads();

    // ---- epilogue: warp w -> slots {w, w+8, w+16, w+24}; lane -> cols 4l.. ----
    {
        float4 rr = ((const float4*)sRel)[lane];
        const float* rrp = &rr.x;
        const float4* gF = (const float4*)fc_w;
        const float4* sCp4 = (const float4*)sCp;
        const float fcb = __ldg(fc_b);

#pragma unroll
        for (int q = 0; q < 4; q++) {
            const int slot = wid + q * 8;
            if (slot >= n) continue;
            float4 ph4 = *(const float4*)(sD + slot * SD_STRIDE + 4 * lane);
            float4 pt4 = *(const float4*)(sD + (32 + slot) * SD_STRIDE + 4 * lane);
            const float* php = &ph4.x;
            const float* ptp = &pt4.x;
            float part = 0.f;
#pragma unroll 2
            for (int c = 0; c < CN; c++) {
                float4 cp = sCp4[c];
                float4 fw = __ldg(&gF[c * 32 + lane]);
                const float* fwp = &fw.x;
#pragma unroll
                for (int j = 0; j < 4; j++) {
                    float g = fmaf(php[j], cp.x,
                              fmaf(ptp[j], cp.z,
                              fmaf(rrp[j], cp.y, cp.w)));
                    g = fmaxf(g, 0.f);
                    part = fmaf(g, fwp[j], part);
                }
            }
#pragma unroll
            for (int s = 16; s; s >>= 1) part += __shfl_xor_sync(0xffffffffu, part, s);
            if (lane == 0) out[sTid[slot]] = part + fcb;
        }
    }
}

// ---------------------------------------------------------------------------
extern "C" void kernel_launch(void* const* d_in, const int* in_sizes, int n_in,
                              void* d_out, int out_size)
{
    const int*   triples = (const int*)d_in[0];
    const float* ent_emb = (const float*)d_in[1];
    const float* rel_emb = (const float*)d_in[2];
    const float* rel_W   = (const float*)d_in[3];
    const float* conv_w  = (const float*)d_in[4];
    const float* conv_b  = (const float*)d_in[5];
    const float* fc_w    = (const float*)d_in[6];
    const float* fc_b    = (const float*)d_in[7];
    float* out = (float*)d_out;

    cudaFuncSetAttribute(k_main, cudaFuncAttributeMaxDynamicSharedMemorySize, SMEM_BYTES);

    k_hist<<<(BNUM + 255) / 256, 256>>>(triples);
    k_scan<<<1, 32>>>();
    k_scatter<<<BNUM / 512, 512>>>(triples);
    k_main<<<RNUM * NCHK, NTHR, SMEM_BYTES>>>(triples, ent_emb, rel_emb, rel_W,
                                              conv_w, conv_b, fc_w, fc_b, out);
}

// round 17
// speedup vs baseline: 1.0622x; 1.0622x over previous
#include <cuda_runtime.h>
#include <cuda_bf16.h>
#include <cstdint>

// Problem constants
#define DN   128      // embedding dim
#define CN   50       // conv channels
#define RNUM 237      // relations
#define BNUM 16384    // triples
#define TB   32       // triple slots per CTA (MMA M = 64 = 32 h + 32 t)
#define NCHK 4        // chunks per relation (capacity 128, validated R15)
#define NTHR 256      // 8 warps

// ---- device scratch ----
__device__ int g_count[RNUM];   // zero at module load; k_scan resets it each run
__device__ int g_start[RNUM];
__device__ int g_cnt[RNUM];
__device__ int g_cursor[RNUM];
__device__ int g_sorted[BNUM];
// Pre-converted, pre-swizzled bf16 W tiles (hi/lo), 32KB per relation each.
// Layout per relation: 2048 uint4 chunks; chunk index = d*16 + ((col16) ^ (d&7))
__device__ uint4 g_WH[RNUM * 2048];
__device__ uint4 g_WL[RNUM * 2048];

// ---------------------------------------------------------------------------
// helpers
// ---------------------------------------------------------------------------
__device__ __forceinline__ uint32_t smem_u32(const void* p) {
    uint32_t a;
    asm("{ .reg .u64 t; cvta.to.shared.u64 t, %1; cvt.u32.u64 %0, t; }" : "=r"(a) : "l"(p));
    return a;
}
__device__ __forceinline__ void ldsm4(unsigned* f, uint32_t addr) {
    asm volatile("ldmatrix.sync.aligned.m8n8.x4.shared.b16 {%0,%1,%2,%3}, [%4];"
                 : "=r"(f[0]), "=r"(f[1]), "=r"(f[2]), "=r"(f[3]) : "r"(addr));
}
__device__ __forceinline__ void ldsm4t(unsigned* f, uint32_t addr) {
    asm volatile("ldmatrix.sync.aligned.m8n8.x4.trans.shared.b16 {%0,%1,%2,%3}, [%4];"
                 : "=r"(f[0]), "=r"(f[1]), "=r"(f[2]), "=r"(f[3]) : "r"(addr));
}
__device__ __forceinline__ void mma16816(float* c, const unsigned* a, unsigned b0, unsigned b1) {
    asm volatile(
        "mma.sync.aligned.m16n8k16.row.col.f32.bf16.bf16.f32 "
        "{%0,%1,%2,%3}, {%4,%5,%6,%7}, {%8,%9}, {%0,%1,%2,%3};"
        : "+f"(c[0]), "+f"(c[1]), "+f"(c[2]), "+f"(c[3])
        : "r"(a[0]), "r"(a[1]), "r"(a[2]), "r"(a[3]), "r"(b0), "r"(b1));
}
// f32 pair -> bf16x2 hi + bf16x2 lo (split precision)
__device__ __forceinline__ void cvt2(float a, float b, unsigned& hi, unsigned& lo) {
    __nv_bfloat16 ah = __float2bfloat16_rn(a);
    __nv_bfloat16 bh = __float2bfloat16_rn(b);
    float ar = a - __bfloat162float(ah);
    float br = b - __bfloat162float(bh);
    __nv_bfloat162 H; H.x = ah; H.y = bh;
    __nv_bfloat162 L; L.x = __float2bfloat16_rn(ar); L.y = __float2bfloat16_rn(br);
    hi = *reinterpret_cast<unsigned*>(&H);
    lo = *reinterpret_cast<unsigned*>(&L);
}

// ---------------------------------------------------------------------------
// Prep 1 (fused): blocks 0..63 -> histogram; blocks 64..300 -> W bf16 convert
// ---------------------------------------------------------------------------
__global__ void k_pre1(const int* __restrict__ triples,
                       const float* __restrict__ rel_W) {
    if (blockIdx.x < 64) {
        __shared__ int sh[RNUM];
        for (int i = threadIdx.x; i < RNUM; i += 256) sh[i] = 0;
        __syncthreads();
        int i = blockIdx.x * 256 + threadIdx.x;
        if (i < BNUM) atomicAdd(&sh[triples[3 * i + 1]], 1);
        __syncthreads();
        for (int i2 = threadIdx.x; i2 < RNUM; i2 += 256) {
            int v = sh[i2];
            if (v) atomicAdd(&g_count[i2], v);
        }
    } else {
        const int r = blockIdx.x - 64;
        const float* Wb = rel_W + (size_t)r * DN * DN;
#pragma unroll
        for (int it = 0; it < 8; it++) {
            int g = it * 256 + threadIdx.x;   // 0..2047 chunk id
            int d = g >> 4;                   // row 0..127
            int c = g & 15;                   // 16B chunk within row
            const float4* src = (const float4*)(Wb + (size_t)d * DN + c * 8);
            float4 u = src[0], v = src[1];
            unsigned h0,l0,h1,l1,h2,l2,h3,l3;
            cvt2(u.x, u.y, h0, l0); cvt2(u.z, u.w, h1, l1);
            cvt2(v.x, v.y, h2, l2); cvt2(v.z, v.w, h3, l3);
            int oi = r * 2048 + d * 16 + (c ^ (d & 7));   // swizzled
            g_WH[oi] = make_uint4(h0, h1, h2, h3);
            g_WL[oi] = make_uint4(l0, l1, l2, l3);
        }
    }
}

__global__ void k_scan() {
    int l = threadIdx.x;
    int vals[8], cnts[8];
    int sum = 0;
#pragma unroll
    for (int j = 0; j < 8; j++) {
        int b = l * 8 + j;
        vals[j] = sum;
        cnts[j] = (b < RNUM) ? g_count[b] : 0;
        sum += cnts[j];
    }
    int x = sum;
#pragma unroll
    for (int sft = 1; sft < 32; sft <<= 1) {
        int y = __shfl_up_sync(0xffffffffu, x, sft);
        if (l >= sft) x += y;
    }
    int off = x - sum;
#pragma unroll
    for (int j = 0; j < 8; j++) {
        int b = l * 8 + j;
        if (b < RNUM) {
            int s = off + vals[j];
            g_start[b]  = s;
            g_cursor[b] = s;
            g_cnt[b]    = cnts[j];
            g_count[b]  = 0;
        }
    }
}

__global__ void k_scatter(const int* __restrict__ triples) {
    __shared__ int lcnt[RNUM];
    __shared__ int lcur[RNUM];
    const int tid = threadIdx.x;
    for (int i = tid; i < RNUM; i += 512) lcnt[i] = 0;
    __syncthreads();
    const int i = blockIdx.x * 512 + tid;
    const int r = triples[3 * i + 1];
    atomicAdd(&lcnt[r], 1);
    __syncthreads();
    for (int b = tid; b < RNUM; b += 512) {
        int c = lcnt[b];
        int base = c ? atomicAdd(&g_cursor[b], c) : 0;
        lcur[b] = base;
    }
    __syncthreads();
    int pos = atomicAdd(&lcur[r], 1);
    g_sorted[pos] = i;
}

// ---------------------------------------------------------------------------
// Main kernel. Tiles: 256B/row, XOR swizzle chunk^=(row&7)  (ldmatrix clean)
// smem: AH 16K | AL 16K | BH 32K | BL 32K | rel/conv/tid  = ~97.4 KB -> 2 CTA/SM
// ---------------------------------------------------------------------------
#define OFF_AH  0
#define OFF_AL  16384
#define OFF_BH  32768
#define OFF_BL  65536
#define OFF_D   0                  // fp32 64 x 132 (33792 B) overlays A(+BH head)
#define SD_STRIDE 132
#define OFF_REL 98304
#define OFF_CP  (OFF_REL + 512)    // 98816
#define OFF_TID (OFF_CP + 800)     // 99616
#define SMEM_BYTES (OFF_TID + 128) // 99744

__global__ __launch_bounds__(NTHR, 2)
void k_main(const int* __restrict__ triples,
            const float* __restrict__ ent_emb,
            const float* __restrict__ rel_emb,
            const float* __restrict__ conv_w,
            const float* __restrict__ conv_b,
            const float* __restrict__ fc_w,
            const float* __restrict__ fc_b,
            float* __restrict__ out)
{
    const int r     = blockIdx.x >> 2;
    const int chunk = blockIdx.x & 3;

    const int cnt  = g_cnt[r];
    const int base = chunk * TB;
    const int n    = min(TB, cnt - base);
    if (n <= 0) return;
    const int gbase = g_start[r] + base;

    extern __shared__ char smc[];
    float* sD   = (float*)(smc + OFF_D);
    float* sRel = (float*)(smc + OFF_REL);
    float* sCp  = (float*)(smc + OFF_CP);
    int*   sTid = (int*)(smc + OFF_TID);

    const int tid  = threadIdx.x;
    const int wid  = tid >> 5;          // 0..7
    const int lane = tid & 31;
    const uint32_t sbase = smem_u32(smc);

    // ---- B staging: pure identity copy of pre-swizzled bf16 tiles ----
    {
        const uint4* gh = g_WH + (size_t)r * 2048;
        const uint4* gl = g_WL + (size_t)r * 2048;
        uint4* dh = (uint4*)(smc + OFF_BH);
        uint4* dl = (uint4*)(smc + OFF_BL);
#pragma unroll
        for (int it = 0; it < 8; it++) {
            int g = it * 256 + tid;
            dh[g] = gh[g];
            dl[g] = gl[g];
        }
    }

    // ---- A staging: entities rows 0..31 = h, 32..63 = t (bf16 hi/lo, swizzled) ----
    {
        const int rp = tid >> 2;                 // row 0..63
        const int q4 = tid & 3;                  // col quarter (32 e's)
        const int c0 = q4 * 32;
        const int slot = rp & 31;
        const bool isH = rp < 32;
        if (slot < n) {
            int i = g_sorted[gbase + slot];
            if (isH && q4 == 0) sTid[slot] = i;
            int ent = isH ? triples[3 * i] : triples[3 * i + 2];
            const float4* ev = (const float4*)(ent_emb + (size_t)ent * DN);
#pragma unroll
            for (int b = 0; b < 4; b++) {
                float4 u = ev[(c0 >> 2) + 2 * b];
                float4 v = ev[(c0 >> 2) + 2 * b + 1];
                unsigned h0,l0,h1,l1,h2,l2,h3,l3;
                cvt2(u.x, u.y, h0, l0); cvt2(u.z, u.w, h1, l1);
                cvt2(v.x, v.y, h2, l2); cvt2(v.z, v.w, h3, l3);
                int ch = q4 * 4 + b;
                int o  = rp * 256 + ((ch ^ (rp & 7)) << 4);
                *(uint4*)(smc + OFF_AH + o) = make_uint4(h0, h1, h2, h3);
                *(uint4*)(smc + OFF_AL + o) = make_uint4(l0, l1, l2, l3);
            }
        } else {
            uint4 Z = make_uint4(0, 0, 0, 0);
#pragma unroll
            for (int b = 0; b < 4; b++) {
                int ch = q4 * 4 + b;
                int o  = rp * 256 + ((ch ^ (rp & 7)) << 4);
                *(uint4*)(smc + OFF_AH + o) = Z;
                *(uint4*)(smc + OFF_AL + o) = Z;
            }
        }
    }

    // ---- stage rel_emb + packed conv params ----
    if (tid < 32) ((float4*)sRel)[tid] = ((const float4*)(rel_emb + (size_t)r * DN))[tid];
    if (tid < CN) {
        float4 cp;
        cp.x = conv_w[3 * tid + 0];
        cp.y = conv_w[3 * tid + 1];
        cp.z = conv_w[3 * tid + 2];
        cp.w = conv_b[tid];
        ((float4*)sCp)[tid] = cp;
    }
    __syncthreads();

    // ---- MMA: warp w -> m-tile (w&3)*16, n-half (w>>2)*64 ----
    // D = Ah*Bh + Al*Bh + Ah*Bl   (validated addressing + swizzle)
    const int m0 = (wid & 3) * 16;
    const int nb = (wid >> 2) * 64;

    float acc[8][4];
#pragma unroll
    for (int tI = 0; tI < 8; tI++)
#pragma unroll
        for (int j = 0; j < 4; j++) acc[tI][j] = 0.f;

    const uint32_t aRow  = m0 + ((lane >> 3) & 1) * 8 + (lane & 7);
    const uint32_t aChnk = (lane >> 4);            // + k0*2
    const uint32_t bDrow = ((lane >> 3) & 1) * 8 + (lane & 7);
    const uint32_t bChnk = (lane >> 4);            // + n0/8

#pragma unroll
    for (int k0 = 0; k0 < 8; k0++) {
        unsigned ah[4], al[4];
        {
            uint32_t ch = (k0 * 2 + aChnk) ^ (aRow & 7);
            uint32_t ad = sbase + aRow * 256 + (ch << 4);
            ldsm4(ah, ad + OFF_AH);
            ldsm4(al, ad + OFF_AL);
        }
#pragma unroll
        for (int np = 0; np < 4; np++) {
            const int n0 = nb + np * 16;
            unsigned bh[4], bl[4];
            uint32_t rowB = k0 * 16 + bDrow;
            uint32_t ch   = ((n0 >> 3) + bChnk) ^ (rowB & 7);
            uint32_t bd   = sbase + rowB * 256 + (ch << 4);
            ldsm4t(bh, bd + OFF_BH);
            ldsm4t(bl, bd + OFF_BL);
            float* c0 = acc[np * 2];
            float* c1 = acc[np * 2 + 1];
            mma16816(c0, ah, bh[0], bh[1]);
            mma16816(c1, ah, bh[2], bh[3]);
            mma16816(c0, al, bh[0], bh[1]);
            mma16816(c1, al, bh[2], bh[3]);
            mma16816(c0, ah, bl[0], bl[1]);
            mma16816(c1, ah, bl[2], bl[3]);
        }
    }
    __syncthreads();   // all warps done reading A/B before sD overlays them

    // ---- store accumulators to sD[row][col] (stride 132) ----
    {
        const int g  = lane >> 2;
        const int tg = lane & 3;
#pragma unroll
        for (int np = 0; np < 4; np++) {
#pragma unroll
            for (int t = 0; t < 2; t++) {
                const float* c = acc[np * 2 + t];
                int col = nb + np * 16 + t * 8 + 2 * tg;
                *(float2*)(sD + (m0 + g) * SD_STRIDE + col)     = make_float2(c[0], c[1]);
                *(float2*)(sD + (m0 + 8 + g) * SD_STRIDE + col) = make_float2(c[2], c[3]);
            }
        }
    }
    __syncthreads();

    // ---- epilogue: warp w -> slots {w, w+8, w+16, w+24}; lane -> cols 4l.. ----
    {
        float4 rr = ((const float4*)sRel)[lane];
        const float* rrp = &rr.x;
        const float4* gF = (const float4*)fc_w;
        const float4* sCp4 = (const float4*)sCp;
        const float fcb = __ldg(fc_b);

        float4 ph4[4], pt4[4];
        int nq = 0;
#pragma unroll
        for (int q = 0; q < 4; q++) {
            const int slot = wid + q * 8;
            if (slot < n) {
                ph4[q] = *(const float4*)(sD + slot * SD_STRIDE + 4 * lane);
                pt4[q] = *(const float4*)(sD + (32 + slot) * SD_STRIDE + 4 * lane);
                nq = q + 1;
            }
        }
        float part[4] = {0.f, 0.f, 0.f, 0.f};
#pragma unroll 2
        for (int c = 0; c < CN; c++) {
            float4 cp = sCp4[c];
            float4 fw = __ldg(&gF[c * 32 + lane]);
            const float* fwp = &fw.x;
            float sj[4];
#pragma unroll
            for (int j = 0; j < 4; j++) sj[j] = fmaf(rrp[j], cp.y, cp.w);
#pragma unroll
            for (int q = 0; q < 4; q++) {
                if (q >= nq) break;
                const float* php = &ph4[q].x;
                const float* ptp = &pt4[q].x;
#pragma unroll
                for (int j = 0; j < 4; j++) {
                    float g = fmaf(php[j], cp.x, fmaf(ptp[j], cp.z, sj[j]));
                    g = fmaxf(g, 0.f);
                    part[q] = fmaf(g, fwp[j], part[q]);
                }
            }
        }
#pragma unroll
        for (int q = 0; q < 4; q++) {
            const int slot = wid + q * 8;
            if (slot >= n) break;
            float v = part[q];
#pragma unroll
            for (int s = 16; s; s >>= 1) v += __shfl_xor_sync(0xffffffffu, v, s);
            if (lane == 0) out[sTid[slot]] = v + fcb;
        }
    }
}

// ---------------------------------------------------------------------------
extern "C" void kernel_launch(void* const* d_in, const int* in_sizes, int n_in,
                              void* d_out, int out_size)
{
    const int*   triples = (const int*)d_in[0];
    const float* ent_emb = (const float*)d_in[1];
    const float* rel_emb = (const float*)d_in[2];
    const float* rel_W   = (const float*)d_in[3];
    const float* conv_w  = (const float*)d_in[4];
    const float* conv_b  = (const float*)d_in[5];
    const float* fc_w    = (const float*)d_in[6];
    const float* fc_b    = (const float*)d_in[7];
    float* out = (float*)d_out;

    cudaFuncSetAttribute(k_main, cudaFuncAttributeMaxDynamicSharedMemorySize, SMEM_BYTES);

    k_pre1<<<64 + RNUM, 256>>>(triples, rel_W);     // hist + W bf16 convert
    k_scan<<<1, 32>>>();
    k_scatter<<<BNUM / 512, 512>>>(triples);
    k_main<<<RNUM * NCHK, NTHR, SMEM_BYTES>>>(triples, ent_emb, rel_emb,
                                              conv_w, conv_b, fc_w, fc_b, out);
}